// round 1
// baseline (speedup 1.0000x reference)
#include <cuda_runtime.h>

#define BATCH 8
#define SEQ   4096
#define EMB   128
#define DH    24
#define DP    25        // padded row (conflict-free: 25 coprime with 32)
#define TQ    64
#define TK    64
#define PSTRIDE 65      // P tile padding (2-way worst case)
#define SCALE 0.08838834764831845f   // 1/sqrt(128)

// Scratch for projected Q,K,V (allowed: __device__ globals, no allocation)
__device__ float Qg[BATCH * SEQ * DH];
__device__ float Kg[BATCH * SEQ * DH];
__device__ float Vg[BATCH * SEQ * DH];

// ---------------------------------------------------------------------------
// Kernel 1: fused Q/K/V projection.  Block = 256 threads handles 64 rows of x.
// Weights (128x72 concat) staged in SMEM; x read via float4 LDG (broadcast
// merged in the coalescer across the 8 col-group threads).
// ---------------------------------------------------------------------------
__global__ __launch_bounds__(256) void proj_kernel(
    const float* __restrict__ x,
    const float* __restrict__ wQ, const float* __restrict__ bQ,
    const float* __restrict__ wK, const float* __restrict__ bK,
    const float* __restrict__ wV, const float* __restrict__ bV)
{
    __shared__ float ws[EMB][72];   // [k][col], cols: 0..23 Q | 24..47 K | 48..71 V
    __shared__ float bs[72];

    int tid = threadIdx.x;
    for (int i = tid; i < EMB * DH; i += 256) {
        int k = i / DH, c = i - k * DH;
        ws[k][c]      = wQ[i];
        ws[k][24 + c] = wK[i];
        ws[k][48 + c] = wV[i];
    }
    if (tid < 24) { bs[tid] = bQ[tid]; bs[24 + tid] = bK[tid]; bs[48 + tid] = bV[tid]; }
    __syncthreads();

    int row0 = blockIdx.x * 64;
    int rt = tid >> 3;           // 0..31
    int ct = tid & 7;            // 0..7  -> 9 output cols each
    int rA = row0 + rt;
    int rB = row0 + 32 + rt;

    float acc0[9], acc1[9];
    #pragma unroll
    for (int j = 0; j < 9; j++) { acc0[j] = 0.f; acc1[j] = 0.f; }

    const float4* xA = reinterpret_cast<const float4*>(x + (size_t)rA * EMB);
    const float4* xB = reinterpret_cast<const float4*>(x + (size_t)rB * EMB);

    #pragma unroll 2
    for (int k4 = 0; k4 < EMB / 4; k4++) {
        float4 a = __ldg(xA + k4);
        float4 b = __ldg(xB + k4);
        float av[4] = {a.x, a.y, a.z, a.w};
        float bv[4] = {b.x, b.y, b.z, b.w};
        #pragma unroll
        for (int kk = 0; kk < 4; kk++) {
            int k = 4 * k4 + kk;
            #pragma unroll
            for (int j = 0; j < 9; j++) {
                float w = ws[k][ct * 9 + j];
                acc0[j] = fmaf(av[kk], w, acc0[j]);
                acc1[j] = fmaf(bv[kk], w, acc1[j]);
            }
        }
    }

    #pragma unroll
    for (int j = 0; j < 9; j++) {
        int c = ct * 9 + j;
        float bias = bs[c];
        float* dst; int cc;
        if (c < 24)      { dst = Qg; cc = c; }
        else if (c < 48) { dst = Kg; cc = c - 24; }
        else             { dst = Vg; cc = c - 48; }
        dst[(size_t)rA * DH + cc] = acc0[j] + bias;
        dst[(size_t)rB * DH + cc] = acc1[j] + bias;
    }
}

// ---------------------------------------------------------------------------
// Kernel 2: fused flash attention + output projection.
// Block = (batch b, 64-query tile). 256 threads.
//   GEMM1 layout: 16x16 threads, 4x4 micro-tile on the 64x64 score tile.
//   GEMM2 layout: (k-split 0..3) x (8 q-row-groups) x (8 d-col-groups),
//                 8x3 register accumulators per thread, conflict-free LDS.
// Online softmax state (m, l, corr) in SMEM, owned per-row by tx==0 lanes.
// ---------------------------------------------------------------------------
__global__ __launch_bounds__(256, 2) void attn_kernel(
    const float* __restrict__ wO, const float* __restrict__ bO,
    float* __restrict__ out)
{
    __shared__ float Qs[TQ][DP];      // later reused as H tile
    __shared__ float Ks[TK][DP];
    __shared__ float Vs[TK][DP];
    __shared__ float Ps[TQ][PSTRIDE];
    __shared__ float m_sh[TQ], l_sh[TQ], corr_sh[TQ];

    int tid = threadIdx.x;
    int b   = blockIdx.y;
    int q0  = blockIdx.x * TQ;
    size_t qbase = ((size_t)b * SEQ + q0) * DH;

    // Load Q tile, pre-scaled by 1/sqrt(E)
    for (int i = tid; i < TQ * DH; i += 256)
        Qs[i / DH][i % DH] = Qg[qbase + i] * SCALE;
    if (tid < TQ) { m_sh[tid] = -1e30f; l_sh[tid] = 0.0f; }

    // GEMM1 thread layout
    int ty = tid >> 4;   // 0..15 -> q rows 4*ty .. 4*ty+3
    int tx = tid & 15;   // 0..15 -> k cols 4*tx .. 4*tx+3
    // GEMM2 thread layout
    int ksg = tid >> 6;          // 0..3  k-split
    int qg  = (tid >> 3) & 7;    // 0..7  -> q rows 8*qg .. 8*qg+7
    int dg  = tid & 7;           // 0..7  -> d cols 3*dg .. 3*dg+2

    float o[8][3];
    #pragma unroll
    for (int i = 0; i < 8; i++)
        #pragma unroll
        for (int j = 0; j < 3; j++) o[i][j] = 0.f;

    __syncthreads();

    for (int kt = 0; kt < SEQ / TK; kt++) {
        // ---- load K,V tile (float4, coalesced; scalar STS into padded rows)
        size_t kbase = ((size_t)b * SEQ + (size_t)kt * TK) * DH;
        const float4* K4 = reinterpret_cast<const float4*>(Kg + kbase);
        const float4* V4 = reinterpret_cast<const float4*>(Vg + kbase);
        for (int i = tid; i < TK * DH / 4; i += 256) {
            float4 kv = __ldg(K4 + i);
            float4 vv = __ldg(V4 + i);
            int f = i * 4; int r = f / DH; int c = f - r * DH;
            Ks[r][c] = kv.x; Ks[r][c+1] = kv.y; Ks[r][c+2] = kv.z; Ks[r][c+3] = kv.w;
            Vs[r][c] = vv.x; Vs[r][c+1] = vv.y; Vs[r][c+2] = vv.z; Vs[r][c+3] = vv.w;
        }
        __syncthreads();

        // ---- GEMM1: 4x4 score micro-tile
        float s[4][4];
        #pragma unroll
        for (int i = 0; i < 4; i++)
            #pragma unroll
            for (int j = 0; j < 4; j++) s[i][j] = 0.f;

        #pragma unroll 8
        for (int d = 0; d < DH; d++) {
            float qv[4], kv[4];
            #pragma unroll
            for (int i = 0; i < 4; i++) qv[i] = Qs[4 * ty + i][d];
            #pragma unroll
            for (int j = 0; j < 4; j++) kv[j] = Ks[4 * tx + j][d];
            #pragma unroll
            for (int i = 0; i < 4; i++)
                #pragma unroll
                for (int j = 0; j < 4; j++)
                    s[i][j] = fmaf(qv[i], kv[j], s[i][j]);
        }

        // ---- online softmax (reduce across the 16 tx lanes)
        float rowmax[4], mnew[4], corr[4], rsum[4];
        #pragma unroll
        for (int i = 0; i < 4; i++)
            rowmax[i] = fmaxf(fmaxf(s[i][0], s[i][1]), fmaxf(s[i][2], s[i][3]));
        #pragma unroll
        for (int off = 8; off; off >>= 1)
            #pragma unroll
            for (int i = 0; i < 4; i++)
                rowmax[i] = fmaxf(rowmax[i], __shfl_xor_sync(0xffffffffu, rowmax[i], off));

        #pragma unroll
        for (int i = 0; i < 4; i++) {
            float mold = m_sh[4 * ty + i];
            mnew[i] = fmaxf(mold, rowmax[i]);
            corr[i] = __expf(mold - mnew[i]);
            rsum[i] = 0.f;
        }
        #pragma unroll
        for (int i = 0; i < 4; i++)
            #pragma unroll
            for (int j = 0; j < 4; j++) {
                float p = __expf(s[i][j] - mnew[i]);
                Ps[4 * ty + i][4 * tx + j] = p;
                rsum[i] += p;
            }
        #pragma unroll
        for (int off = 8; off; off >>= 1)
            #pragma unroll
            for (int i = 0; i < 4; i++)
                rsum[i] += __shfl_xor_sync(0xffffffffu, rsum[i], off);

        if (tx == 0) {
            #pragma unroll
            for (int i = 0; i < 4; i++) {
                int r = 4 * ty + i;
                m_sh[r]    = mnew[i];
                corr_sh[r] = corr[i];
                l_sh[r]    = l_sh[r] * corr[i] + rsum[i];
            }
        }
        __syncthreads();

        // ---- GEMM2: O += P * V  (k-split partials in registers)
        float cr[8];
        #pragma unroll
        for (int i = 0; i < 8; i++) cr[i] = corr_sh[8 * qg + i];
        #pragma unroll
        for (int i = 0; i < 8; i++)
            #pragma unroll
            for (int j = 0; j < 3; j++) o[i][j] *= cr[i];

        int k0 = ksg * 16;
        #pragma unroll 4
        for (int k = 0; k < 16; k++) {
            float v0 = Vs[k0 + k][3 * dg];
            float v1 = Vs[k0 + k][3 * dg + 1];
            float v2 = Vs[k0 + k][3 * dg + 2];
            #pragma unroll
            for (int i = 0; i < 8; i++) {
                float p = Ps[8 * qg + i][k0 + k];
                o[i][0] = fmaf(p, v0, o[i][0]);
                o[i][1] = fmaf(p, v1, o[i][1]);
                o[i][2] = fmaf(p, v2, o[i][2]);
            }
        }
        __syncthreads();
    }

    // ---- merge k-split partials into H (reuse Qs), normalized by 1/l
    float linv[8];
    #pragma unroll
    for (int i = 0; i < 8; i++) linv[i] = 1.0f / l_sh[8 * qg + i];

    #pragma unroll
    for (int phase = 0; phase < 4; phase++) {
        if (ksg == phase) {
            #pragma unroll
            for (int i = 0; i < 8; i++)
                #pragma unroll
                for (int j = 0; j < 3; j++) {
                    float v = o[i][j] * linv[i];
                    if (phase == 0) Qs[8 * qg + i][3 * dg + j]  = v;
                    else            Qs[8 * qg + i][3 * dg + j] += v;
                }
        }
        __syncthreads();
    }

    // ---- fused output projection: out[64][128] = H[64][24] @ wO + bO
    size_t obase = ((size_t)b * SEQ + q0) * EMB;
    for (int idx = tid; idx < TQ * EMB; idx += 256) {
        int q = idx >> 7;
        int e = idx & 127;
        float acc = __ldg(&bO[e]);
        #pragma unroll
        for (int d = 0; d < DH; d++)
            acc = fmaf(Qs[q][d], __ldg(&wO[d * EMB + e]), acc);
        out[obase + idx] = acc;
    }
}

// ---------------------------------------------------------------------------
extern "C" void kernel_launch(void* const* d_in, const int* in_sizes, int n_in,
                              void* d_out, int out_size)
{
    const float* x  = (const float*)d_in[0];
    const float* wQ = (const float*)d_in[1];
    const float* bQ = (const float*)d_in[2];
    const float* wK = (const float*)d_in[3];
    const float* bK = (const float*)d_in[4];
    const float* wV = (const float*)d_in[5];
    const float* bV = (const float*)d_in[6];
    const float* wO = (const float*)d_in[7];
    const float* bO = (const float*)d_in[8];
    float* out = (float*)d_out;

    proj_kernel<<<BATCH * SEQ / 64, 256>>>(x, wQ, bQ, wK, bK, wV, bV);
    attn_kernel<<<dim3(SEQ / TQ, BATCH), 256>>>(wO, bO, out);
}